// round 2
// baseline (speedup 1.0000x reference)
#include <cuda_runtime.h>

#define NN 100000
#define EE 500000
#define DD 128
#define RR 10
#define EPS 1e-5f

// ---------------- scratch (device globals; no allocation allowed) ----------
__device__ float g_agg_in [NN * DD];
__device__ float g_agg_out[NN * DD];
__device__ float g_out    [NN * DD];
__device__ float g_x      [NN * DD];
__device__ int   g_deg_s  [NN];
__device__ int   g_deg_d  [NN];
__device__ float g_dinv_s [NN];
__device__ float g_dinv_d [NN];
__device__ float g_scale_in [EE];
__device__ float g_scale_out[EE];
__device__ float g_stats  [2 * DD];
__device__ float g_r1     [RR * DD];

// ---------------- small helpers -------------------------------------------
__device__ __forceinline__ unsigned long long pk2(float lo, float hi) {
    unsigned long long r;
    asm("mov.b64 %0, {%1, %2};" : "=l"(r) : "f"(lo), "f"(hi));
    return r;
}
__device__ __forceinline__ void upk2(unsigned long long v, float& lo, float& hi) {
    asm("mov.b64 {%0, %1}, %2;" : "=f"(lo), "=f"(hi) : "l"(v));
}
__device__ __forceinline__ void fma2(unsigned long long& d,
                                     unsigned long long a, unsigned long long b) {
    asm("fma.rn.f32x2 %0, %1, %2, %0;" : "+l"(d) : "l"(a), "l"(b));
}
__device__ __forceinline__ void red_v4(float* p, float4 v) {
    asm volatile("red.global.add.v4.f32 [%0], {%1, %2, %3, %4};"
                 :: "l"(p), "f"(v.x), "f"(v.y), "f"(v.z), "f"(v.w) : "memory");
}

// ---------------- degree / scale precompute --------------------------------
__global__ void k_zero_deg() {
    int i = blockIdx.x * blockDim.x + threadIdx.x;
    int stride = gridDim.x * blockDim.x;
    for (int n = i; n < NN; n += stride) { g_deg_s[n] = 0; g_deg_d[n] = 0; }
}

__global__ void k_degree(const int* __restrict__ src, const int* __restrict__ dst) {
    int e = blockIdx.x * blockDim.x + threadIdx.x;
    if (e < EE) {
        atomicAdd(&g_deg_s[src[e]], 1);
        atomicAdd(&g_deg_d[dst[e]], 1);
    }
}

__global__ void k_dinv() {
    int n = blockIdx.x * blockDim.x + threadIdx.x;
    if (n < NN) {
        int ds = g_deg_s[n], dd = g_deg_d[n];
        g_dinv_s[n] = (ds > 0) ? (1.0f / sqrtf((float)ds)) : 0.0f;
        g_dinv_d[n] = (dd > 0) ? (1.0f / sqrtf((float)dd)) : 0.0f;
    }
}

__global__ void k_scales(const int* __restrict__ src, const int* __restrict__ dst) {
    int e = blockIdx.x * blockDim.x + threadIdx.x;
    if (e < EE) {
        int s = src[e], d = dst[e];
        g_scale_in [e] = g_dinv_s[s] * g_dinv_s[d];
        g_scale_out[e] = g_dinv_d[d] * g_dinv_d[s];
    }
}

// ---------------- per-layer zero -------------------------------------------
__global__ void k_zero_layer() {
    int i = blockIdx.x * blockDim.x + threadIdx.x;
    int stride = gridDim.x * blockDim.x;
    const int n4 = NN * DD / 4;
    float4 z = make_float4(0.f, 0.f, 0.f, 0.f);
    float4* a = (float4*)g_agg_in;
    float4* b = (float4*)g_agg_out;
    for (int p = i; p < n4; p += stride) { a[p] = z; b[p] = z; }
    if (i < 2 * DD) g_stats[i] = 0.f;
}

// ---------------- edge aggregation (warp per edge) --------------------------
__global__ void k_edge_agg(const float* __restrict__ x, const float* __restrict__ r,
                           const int* __restrict__ src, const int* __restrict__ dst,
                           const int* __restrict__ typ) {
    __shared__ float rs[RR * DD];
    for (int i = threadIdx.x; i < RR * DD; i += blockDim.x) rs[i] = r[i];
    __syncthreads();

    int gtid  = blockIdx.x * blockDim.x + threadIdx.x;
    int warp  = gtid >> 5;
    int lane  = gtid & 31;
    int nwarp = (gridDim.x * blockDim.x) >> 5;
    const float4* x4 = (const float4*)x;

    for (int e = warp; e < EE; e += nwarp) {
        int s = src[e], d = dst[e], t = typ[e];
        float si = g_scale_in[e], so = g_scale_out[e];
        float4 rv = *(const float4*)&rs[t * DD + lane * 4];
        float4 xd = x4[d * 32 + lane];
        float4 xs = x4[s * 32 + lane];
        float4 mi = make_float4(si * xd.x * rv.x, si * xd.y * rv.y,
                                si * xd.z * rv.z, si * xd.w * rv.w);
        float4 mo = make_float4(so * xs.x * rv.x, so * xs.y * rv.y,
                                so * xs.z * rv.z, so * xs.w * rv.w);
        red_v4(&g_agg_in [s * DD + lane * 4], mi);
        red_v4(&g_agg_out[d * DD + lane * 4], mo);
    }
}

// ---------------- fused 3-chunk GEMM: out = (Ain@Win + Aout@Wout + (x*lr)@Wloop)/3 + bias
// 128x128 block tile, K = 3 chunks x 128, Kc=32 smem slices, fma.rn.f32x2 inner.
__global__ __launch_bounds__(256, 2)
void k_gemm(const float* __restrict__ x,
            const float* __restrict__ B0, const float* __restrict__ B1,
            const float* __restrict__ B2,
            const float* __restrict__ lr, const float* __restrict__ bias) {
    __shared__ float Ast[32][132];   // [k][row], transposed
    __shared__ float Bs [32][132];   // [k][col]

    const int tid = threadIdx.x;
    const int tx = tid & 15;         // column group (8 cols)
    const int ty = tid >> 4;         // row group (8 rows)
    const int rowBase = blockIdx.x * 128;

    unsigned long long acc[8][4];
#pragma unroll
    for (int i = 0; i < 8; i++)
#pragma unroll
        for (int j = 0; j < 4; j++) acc[i][j] = 0ULL;

    for (int c = 0; c < 3; c++) {
        const float* A = (c == 0) ? g_agg_in : (c == 1) ? g_agg_out : x;
        const float* B = (c == 0) ? B0 : (c == 1) ? B1 : B2;
        for (int ks = 0; ks < 4; ks++) {
            __syncthreads();
            // load A slice 128 rows x 32 k (transposed store)
            {
                int k4 = tid & 7;    // float4 index along k
                int r0 = tid >> 3;   // 0..31
#pragma unroll
                for (int rr = 0; rr < 4; rr++) {
                    int row = r0 + rr * 32;
                    int grow = rowBase + row;
                    float4 v = make_float4(0.f, 0.f, 0.f, 0.f);
                    if (grow < NN)
                        v = *(const float4*)&A[(size_t)grow * DD + ks * 32 + k4 * 4];
                    Ast[k4 * 4 + 0][row] = v.x;
                    Ast[k4 * 4 + 1][row] = v.y;
                    Ast[k4 * 4 + 2][row] = v.z;
                    Ast[k4 * 4 + 3][row] = v.w;
                }
            }
            // load B slice 32 k x 128 col (straight)
            {
                int c4 = tid & 31;
                int k0 = tid >> 5;   // 0..7
#pragma unroll
                for (int p = 0; p < 4; p++) {
                    int kk = k0 + p * 8;
                    int gk = ks * 32 + kk;
                    float4 v = *(const float4*)&B[gk * DD + c4 * 4];
                    if (c == 2) {
                        float sc = lr[gk];
                        v.x *= sc; v.y *= sc; v.z *= sc; v.w *= sc;
                    }
                    *(float4*)&Bs[kk][c4 * 4] = v;
                }
            }
            __syncthreads();
#pragma unroll 4
            for (int k = 0; k < 32; k++) {
                float4 a0 = *(const float4*)&Ast[k][ty * 8];
                float4 a1 = *(const float4*)&Ast[k][ty * 8 + 4];
                float4 b0 = *(const float4*)&Bs[k][tx * 8];
                float4 b1 = *(const float4*)&Bs[k][tx * 8 + 4];
                unsigned long long bp[4];
                bp[0] = pk2(b0.x, b0.y); bp[1] = pk2(b0.z, b0.w);
                bp[2] = pk2(b1.x, b1.y); bp[3] = pk2(b1.z, b1.w);
                float av[8] = {a0.x, a0.y, a0.z, a0.w, a1.x, a1.y, a1.z, a1.w};
#pragma unroll
                for (int i = 0; i < 8; i++) {
                    unsigned long long ap = pk2(av[i], av[i]);
#pragma unroll
                    for (int j = 0; j < 4; j++) fma2(acc[i][j], ap, bp[j]);
                }
            }
        }
    }

    const float third = 1.0f / 3.0f;
#pragma unroll
    for (int i = 0; i < 8; i++) {
        int grow = rowBase + ty * 8 + i;
        if (grow < NN) {
#pragma unroll
            for (int j = 0; j < 4; j++) {
                float lo, hi;
                upk2(acc[i][j], lo, hi);
                int col = tx * 8 + j * 2;
                g_out[(size_t)grow * DD + col]     = lo * third + bias[col];
                g_out[(size_t)grow * DD + col + 1] = hi * third + bias[col + 1];
            }
        }
    }
}

// ---------------- batchnorm stats + normalize+tanh -------------------------
__global__ void k_colstats() {
    int j = threadIdx.x;  // 128
    float s = 0.f, q = 0.f;
    for (int n = blockIdx.x; n < NN; n += gridDim.x) {
        float v = g_out[(size_t)n * DD + j];
        s += v; q += v * v;
    }
    atomicAdd(&g_stats[j], s);
    atomicAdd(&g_stats[DD + j], q);
}

__global__ void k_bn_tanh(float* __restrict__ xo) {
    int j = threadIdx.x;  // 128
    float mean = g_stats[j] * (1.0f / NN);
    float var  = g_stats[DD + j] * (1.0f / NN) - mean * mean;
    float inv  = 1.0f / sqrtf(var + EPS);
    for (int n = blockIdx.x; n < NN; n += gridDim.x) {
        float v = g_out[(size_t)n * DD + j];
        xo[(size_t)n * DD + j] = tanhf((v - mean) * inv);
    }
}

// ---------------- relation transform r' = r @ W -----------------------------
__global__ void k_relmm(const float* __restrict__ r, const float* __restrict__ w,
                        float* __restrict__ ro) {
    int idx = blockIdx.x * blockDim.x + threadIdx.x;
    if (idx < RR * DD) {
        int i = idx / DD, j = idx % DD;
        float s = 0.f;
        for (int k = 0; k < DD; k++) s += r[i * DD + k] * w[k * DD + j];
        ro[idx] = s;
    }
}

// ---------------- launch ----------------------------------------------------
extern "C" void kernel_launch(void* const* d_in, const int* in_sizes, int n_in,
                              void* d_out, int out_size) {
    const float* x0       = (const float*)d_in[0];
    const float* r0       = (const float*)d_in[1];
    const float* w_in     = (const float*)d_in[2];
    const float* w_out    = (const float*)d_in[3];
    const float* w_loop   = (const float*)d_in[4];
    const float* w_rel    = (const float*)d_in[5];
    const float* loop_rel = (const float*)d_in[6];
    const float* bias     = (const float*)d_in[7];
    const int*   esrc     = (const int*)d_in[8];
    const int*   edst     = (const int*)d_in[9];
    const int*   etyp     = (const int*)d_in[10];

    float* out      = (float*)d_out;
    float* x_final  = out;
    float* r_final  = out + (size_t)NN * DD;

    const int GEMM_BLOCKS = (NN + 127) / 128;  // 782

    // graph-structure precompute (shared by both layers)
    k_zero_deg<<<256, 256>>>();
    k_degree<<<(EE + 255) / 256, 256>>>(esrc, edst);
    k_dinv<<<(NN + 255) / 256, 256>>>();
    k_scales<<<(EE + 255) / 256, 256>>>(esrc, edst);

    // ---- layer 0 ----
    k_zero_layer<<<4096, 256>>>();
    k_edge_agg<<<2048, 256>>>(x0, r0, esrc, edst, etyp);
    k_gemm<<<GEMM_BLOCKS, 256>>>(x0, w_in, w_out, w_loop, loop_rel, bias);
    k_colstats<<<512, 128>>>();
    k_bn_tanh<<<1024, 128>>>(g_x);
    k_relmm<<<(RR * DD + 255) / 256, 256>>>(r0, w_rel, g_r1);

    // ---- layer 1 ----
    k_zero_layer<<<4096, 256>>>();
    k_edge_agg<<<2048, 256>>>(g_x, g_r1, esrc, edst, etyp);
    k_gemm<<<GEMM_BLOCKS, 256>>>(g_x, w_in + DD * DD, w_out + DD * DD,
                                 w_loop + DD * DD, loop_rel + DD, bias + DD);
    k_colstats<<<512, 128>>>();
    k_bn_tanh<<<1024, 128>>>(x_final);
    k_relmm<<<(RR * DD + 255) / 256, 256>>>(g_r1, w_rel + DD * DD, r_final);
}